// round 4
// baseline (speedup 1.0000x reference)
#include <cuda_runtime.h>
#include <cuda_bf16.h>
#include <math.h>

// Problem constants
#define BB 32
#define SS 1024
#define DIN 128
#define HH 256
#define G4H 1024          // 4*H
#define HCAT 512          // 2*H

typedef unsigned long long ull;

// ---------------- scratch (device globals; no cudaMalloc allowed) ----------
__device__ float g_xp[2u * SS * BB * G4H];        // [dir][s][b][4H]
__device__ float g_hcat0[(size_t)BB * SS * HCAT]; // [b][s][512]
__device__ float g_hcat1[(size_t)BB * SS * HCAT];
__device__ float g_ctx[(size_t)BB * SS * HCAT];
__device__ float g_h[2 * 2 * BB * HH];            // [dir][parity][b][k]
__device__ float g_s[BB * SS];
__device__ float g_mx[BB];
__device__ unsigned g_flags[2][2][64];            // [layer][dir][cta]

// ---------------------------------------------------------------------------
__device__ __forceinline__ float sigf(float x) { return 1.0f / (1.0f + __expf(-x)); }
__device__ __forceinline__ float tanhfast(float x) { return 1.0f - 2.0f / (__expf(2.0f * x) + 1.0f); }

__device__ __forceinline__ unsigned ld_acq(const unsigned* p) {
    unsigned v;
    asm volatile("ld.acquire.gpu.u32 %0, [%1];" : "=r"(v) : "l"(p));
    return v;
}
__device__ __forceinline__ void st_rel(unsigned* p, unsigned v) {
    asm volatile("st.release.gpu.u32 [%0], %1;" :: "l"(p), "r"(v) : "memory");
}
__device__ __forceinline__ void ffma2(ull& acc, ull a, ull b) {
    asm("fma.rn.f32x2 %0, %1, %2, %0;" : "+l"(acc) : "l"(a), "l"(b));
}

__global__ void reset_kernel() {
    ((unsigned*)g_flags)[threadIdx.x] = 0u;   // 256 flags
}

// ---------------------------------------------------------------------------
// Tiled FP32 GEMM: out[m,n] = sum_k A[m,k] * W[n,k] + bias[n]
// BM=128, BN=64, BK=16, 256 threads, 8x4 per-thread tile.
// SRC: 0 = A param (x), 1 = g_hcat0, 2 = g_ctx
// EPI: 0 = proj (writes g_xp, dual dir weights), 1 = head (writes out param)
// ---------------------------------------------------------------------------
template <int SRC, int EPI>
__global__ __launch_bounds__(256) void gemm_kernel(
    const float* __restrict__ A_in, int K,
    const float* __restrict__ Wf, const float* __restrict__ Wb,
    const float* __restrict__ bf, const float* __restrict__ bb,
    float* __restrict__ out_p)
{
    __shared__ float As[16][132];
    __shared__ float Bs[16][68];

    const float* A = (SRC == 0) ? A_in : (SRC == 1 ? g_hcat0 : g_ctx);

    const int t  = threadIdx.x;
    const int tx = t & 15;
    const int ty = t >> 4;
    const int m0 = blockIdx.x * 128;
    const int n0 = blockIdx.y * 64;

    const float* Wp;
    const float* biasp;
    int wrow0;
    if (EPI == 0) {
        if (n0 < 1024) { Wp = Wf; biasp = bf; wrow0 = n0; }
        else           { Wp = Wb; biasp = bb; wrow0 = n0 - 1024; }
    } else {
        Wp = Wf; biasp = bf; wrow0 = n0;
    }

    float acc[8][4];
#pragma unroll
    for (int i = 0; i < 8; i++)
#pragma unroll
        for (int j = 0; j < 4; j++) acc[i][j] = 0.0f;

    const int nkt = K >> 4;
    for (int kt = 0; kt < nkt; kt++) {
        const int k0 = kt << 4;
#pragma unroll
        for (int r = 0; r < 2; r++) {
            int idx = t + r * 256;
            int row = idx >> 2;
            int kq  = idx & 3;
            float4 v = *(const float4*)&A[(size_t)(m0 + row) * K + k0 + kq * 4];
            As[kq * 4 + 0][row] = v.x;
            As[kq * 4 + 1][row] = v.y;
            As[kq * 4 + 2][row] = v.z;
            As[kq * 4 + 3][row] = v.w;
        }
        {
            int row = t >> 2;
            int kq  = t & 3;
            float4 v = *(const float4*)&Wp[(size_t)(wrow0 + row) * K + k0 + kq * 4];
            Bs[kq * 4 + 0][row] = v.x;
            Bs[kq * 4 + 1][row] = v.y;
            Bs[kq * 4 + 2][row] = v.z;
            Bs[kq * 4 + 3][row] = v.w;
        }
        __syncthreads();
#pragma unroll
        for (int kk = 0; kk < 16; kk++) {
            float af[8], bfr[4];
            *(float4*)&af[0]  = *(const float4*)&As[kk][ty * 8];
            *(float4*)&af[4]  = *(const float4*)&As[kk][ty * 8 + 4];
            *(float4*)&bfr[0] = *(const float4*)&Bs[kk][tx * 4];
#pragma unroll
            for (int i = 0; i < 8; i++)
#pragma unroll
                for (int j = 0; j < 4; j++)
                    acc[i][j] = fmaf(af[i], bfr[j], acc[i][j]);
        }
        __syncthreads();
    }

#pragma unroll
    for (int i = 0; i < 8; i++) {
        int m = m0 + ty * 8 + i;
        int b = m >> 10;
        int s = m & 1023;
#pragma unroll
        for (int j = 0; j < 4; j++) {
            int c = tx * 4 + j;
            float v = acc[i][j] + biasp[wrow0 + c];
            if (EPI == 0) {
                int ng  = n0 + c;
                int dir = ng >> 10;
                int g   = ng & 1023;
                g_xp[((size_t)(dir * SS + s) * BB + b) * G4H + g] = v;
            } else {
                out_p[(size_t)m * 128 + (n0 + c)] = v;
            }
        }
    }
}

// ---------------------------------------------------------------------------
// Persistent bidirectional LSTM layer. 128 CTAs (64/dir), 128 threads.
// CTA owns 4 hidden units (16 W_hh rows, SMEM). Per-direction flag barrier,
// release/acquire (no atomics, no fences). f32x2 packed FMAs over k-pairs.
// ---------------------------------------------------------------------------
#define WST 258                         // padded k-stride (floats)
#define LSTM_SMEM ((16 * WST + 32 * WST + 512) * 4)

__global__ __launch_bounds__(128, 1) void lstm_kernel(
    const float* __restrict__ whf, const float* __restrict__ whb, int layer)
{
    extern __shared__ float sm[];
    float* sm_w = sm;                    // [16][WST]
    float* sm_h = sm + 16 * WST;         // [32][WST]
    float* sm_g = sm + 48 * WST;         // [16][32]

    const int t     = threadIdx.x;
    const int dir   = blockIdx.x >> 6;
    const int slice = blockIdx.x & 63;
    const float* W  = dir ? whb : whf;
    float* hout     = (layer == 0) ? g_hcat0 : g_hcat1;
    unsigned* flags = g_flags[layer][dir];

    // load weight slice: rows r = G*4+u -> W[(G*256 + slice*4 + u)][k]
    for (int e = t; e < 4096; e += 128) {
        int r = e >> 8, k = e & 255;
        int grow = ((r >> 2) << 8) + (slice << 2) + (r & 3);
        sm_w[r * WST + k] = W[(size_t)grow * HH + k];
    }

    // compute mapping: 2 rows x 2 batches (b, b+16) per thread
    const int rp = t >> 4;               // 0..7
    const int bp = t & 15;               // 0..15
    const int r0 = rp * 2, r1 = rp * 2 + 1;
    const int gr0 = ((r0 >> 2) << 8) + (slice << 2) + (r0 & 3);
    const int gr1 = ((r1 >> 2) << 8) + (slice << 2) + (r1 & 3);

    // activation mapping: one (u, b) per thread; warp-coalesced units
    const int au = t & 3;                // 0..3
    const int ab = t >> 2;               // 0..31
    const int myu = (slice << 2) + au;
    float cstate = 0.0f;

    // init h parity 0 (layout [dir][parity][b][k])
    g_h[((dir * 2 + 0) * BB + ab) * HH + myu] = 0.0f;

    // barrier phase 1 (init visible)
    unsigned phase = 1;
    __syncthreads();
    if (t == 0) st_rel(&flags[slice], phase);
    if (t < 32) {
        for (;;) {
            unsigned v0 = ld_acq(flags + t);
            unsigned v1 = ld_acq(flags + 32 + t);
            if (__all_sync(0xFFFFFFFFu, (v0 >= phase) && (v1 >= phase))) break;
        }
    }
    __syncthreads();

    const float* xpd = g_xp + (size_t)dir * SS * BB * G4H;

    for (int s = 0; s < SS; s++) {
        const int p    = s & 1;
        const int tcur = dir ? (SS - 1 - s) : s;

        // prefetch xp for this thread's 4 outputs
        const float* xpb = xpd + (size_t)tcur * BB * G4H;
        float x00 = __ldcg(&xpb[(size_t)bp * G4H + gr0]);
        float x01 = __ldcg(&xpb[(size_t)(bp + 16) * G4H + gr0]);
        float x10 = __ldcg(&xpb[(size_t)bp * G4H + gr1]);
        float x11 = __ldcg(&xpb[(size_t)(bp + 16) * G4H + gr1]);

        // stage h_prev [b][k] -> padded smem (L2-direct loads; L1 never holds h)
        {
            const float4* gsrc = (const float4*)(g_h + (dir * 2 + p) * BB * HH);
            for (int e = t; e < 2048; e += 128) {
                float4 v = __ldcg(gsrc + e);
                int row = e >> 6;
                int col = e & 63;
                float2* d = (float2*)(sm_h + row * WST) + col * 2;
                d[0] = make_float2(v.x, v.y);
                d[1] = make_float2(v.z, v.w);
            }
        }
        __syncthreads();

        // 2 rows x 2 batches, packed f32x2 over k-pairs
        ull a00 = 0ull, a01 = 0ull, a10 = 0ull, a11 = 0ull;
        const ull* pw0 = (const ull*)(sm_w + r0 * WST);
        const ull* pw1 = (const ull*)(sm_w + r1 * WST);
        const ull* ph0 = (const ull*)(sm_h + bp * WST);
        const ull* ph1 = (const ull*)(sm_h + (bp + 16) * WST);
#pragma unroll 8
        for (int kk = 0; kk < 128; kk++) {
            ull w0 = pw0[kk];
            ull w1 = pw1[kk];
            ull h0 = ph0[kk];
            ull h1 = ph1[kk];
            ffma2(a00, w0, h0);
            ffma2(a01, w0, h1);
            ffma2(a10, w1, h0);
            ffma2(a11, w1, h1);
        }
        {
            float2 v00 = *(float2*)&a00, v01 = *(float2*)&a01;
            float2 v10 = *(float2*)&a10, v11 = *(float2*)&a11;
            sm_g[r0 * 32 + bp]      = v00.x + v00.y + x00;
            sm_g[r0 * 32 + bp + 16] = v01.x + v01.y + x01;
            sm_g[r1 * 32 + bp]      = v10.x + v10.y + x10;
            sm_g[r1 * 32 + bp + 16] = v11.x + v11.y + x11;
        }
        __syncthreads();

        // activation: gates i,f,g,o at rows G*4+u
        {
            float gi = sm_g[(0 * 4 + au) * 32 + ab];
            float gf = sm_g[(1 * 4 + au) * 32 + ab];
            float gg = sm_g[(2 * 4 + au) * 32 + ab];
            float go = sm_g[(3 * 4 + au) * 32 + ab];
            cstate = sigf(gf) * cstate + sigf(gi) * tanhfast(gg);
            float hv = sigf(go) * tanhfast(cstate);
            g_h[((dir * 2 + (p ^ 1)) * BB + ab) * HH + myu] = hv;
            hout[((size_t)ab * SS + tcur) * HCAT + dir * HH + myu] = hv;
        }

        if (s == SS - 1) break;

        // per-direction flag barrier (release/acquire, no atomics)
        phase++;
        __syncthreads();
        if (t == 0) st_rel(&flags[slice], phase);
        if (t < 32) {
            for (;;) {
                unsigned v0 = ld_acq(flags + t);
                unsigned v1 = ld_acq(flags + 32 + t);
                if (__all_sync(0xFFFFFFFFu, (v0 >= phase) && (v1 >= phase))) break;
            }
        }
        __syncthreads();
    }
}

// ---------------------------------------------------------------------------
// attention score: s[b,t] = dot(h[b,t,:], attn_w) + attn_b ; per-b max
// ---------------------------------------------------------------------------
__global__ __launch_bounds__(256) void score_kernel(
    const float* __restrict__ attn_w, const float* __restrict__ attn_b)
{
    __shared__ float aw[HCAT];
    __shared__ float red[8];
    const int b = blockIdx.x;
    const int t = threadIdx.x;
    const int w = t >> 5, l = t & 31;
    for (int j = t; j < HCAT; j += 256) aw[j] = attn_w[j];
    __syncthreads();

    const float ab = attn_b[0];
    float mloc = -1e30f;
    for (int tt = w; tt < SS; tt += 8) {
        const float* hp = g_hcat1 + ((size_t)b * SS + tt) * HCAT;
        float sum = 0.f;
        for (int j = l; j < HCAT; j += 32) sum = fmaf(hp[j], aw[j], sum);
#pragma unroll
        for (int o = 16; o > 0; o >>= 1) sum += __shfl_xor_sync(0xFFFFFFFFu, sum, o);
        float sv = sum + ab;
        if (l == 0) g_s[b * SS + tt] = sv;
        mloc = fmaxf(mloc, sv);
    }
    if (l == 0) red[w] = mloc;
    __syncthreads();
    if (t == 0) {
        float m = red[0];
#pragma unroll
        for (int i = 1; i < 8; i++) m = fmaxf(m, red[i]);
        g_mx[b] = m;
    }
}

// ---------------------------------------------------------------------------
// cumulative softmax context: ctx[b,t,:] = cumsum(e*h)/cumsum(e)
// ---------------------------------------------------------------------------
__global__ __launch_bounds__(512) void ctx_kernel()
{
    const int b = blockIdx.x;
    const int j = threadIdx.x;
    const float mx = g_mx[b];
    float num = 0.f, den = 0.f;
    const float* sb = g_s + b * SS;
    for (int t = 0; t < SS; t++) {
        float e = __expf(sb[t] - mx);
        den += e;
        size_t off = ((size_t)b * SS + t) * HCAT + j;
        num = fmaf(e, g_hcat1[off], num);
        g_ctx[off] = num / den;
    }
}

// ---------------------------------------------------------------------------
extern "C" void kernel_launch(void* const* d_in, const int* in_sizes, int n_in,
                              void* d_out, int out_size)
{
    const float* x        = (const float*)d_in[0];
    const float* w_ih_l0f = (const float*)d_in[1];
    const float* w_hh_l0f = (const float*)d_in[2];
    const float* b_l0f    = (const float*)d_in[3];
    const float* w_ih_l0b = (const float*)d_in[4];
    const float* w_hh_l0b = (const float*)d_in[5];
    const float* b_l0b    = (const float*)d_in[6];
    const float* w_ih_l1f = (const float*)d_in[7];
    const float* w_hh_l1f = (const float*)d_in[8];
    const float* b_l1f    = (const float*)d_in[9];
    const float* w_ih_l1b = (const float*)d_in[10];
    const float* w_hh_l1b = (const float*)d_in[11];
    const float* b_l1b    = (const float*)d_in[12];
    const float* attn_w   = (const float*)d_in[13];
    const float* attn_b   = (const float*)d_in[14];
    const float* head_w   = (const float*)d_in[15];
    const float* head_b   = (const float*)d_in[16];
    float* out = (float*)d_out;

    cudaFuncSetAttribute(lstm_kernel, cudaFuncAttributeMaxDynamicSharedMemorySize, LSTM_SMEM);

    reset_kernel<<<1, 256>>>();

    // layer 0: projection + recurrence
    gemm_kernel<0, 0><<<dim3(256, 32), 256>>>(x, DIN, w_ih_l0f, w_ih_l0b, b_l0f, b_l0b, nullptr);
    lstm_kernel<<<128, 128, LSTM_SMEM>>>(w_hh_l0f, w_hh_l0b, 0);

    // layer 1: projection (A = g_hcat0) + recurrence
    gemm_kernel<1, 0><<<dim3(256, 32), 256>>>(nullptr, HCAT, w_ih_l1f, w_ih_l1b, b_l1f, b_l1b, nullptr);
    lstm_kernel<<<128, 128, LSTM_SMEM>>>(w_hh_l1f, w_hh_l1b, 1);

    // attention + context + head
    score_kernel<<<32, 256>>>(attn_w, attn_b);
    ctx_kernel<<<32, 512>>>();
    gemm_kernel<2, 1><<<dim3(256, 2), 256>>>(nullptr, HCAT, head_w, nullptr, head_b, nullptr, out);
}

// round 7
// speedup vs baseline: 1.6814x; 1.6814x over previous
#include <cuda_runtime.h>
#include <cuda_bf16.h>
#include <math.h>

// Problem constants
#define BB 32
#define SS 1024
#define DIN 128
#define HH 256
#define G4H 1024          // 4*H
#define HCAT 512          // 2*H

typedef unsigned long long ull;

// ---------------- scratch (device globals; no cudaMalloc allowed) ----------
__device__ float g_xp[2u * SS * BB * G4H];        // [dir][s][b][4H]
__device__ float g_hcat0[(size_t)BB * SS * HCAT]; // [b][s][512]
__device__ float g_hcat1[(size_t)BB * SS * HCAT];
__device__ float g_ctx[(size_t)BB * SS * HCAT];
__device__ float g_h[2 * 2 * BB * HH];            // [dir][parity][b][k]
__device__ float g_s[BB * SS];
__device__ float g_mx[BB];
__device__ unsigned g_bar[4][32];                 // [layer*2+dir][pad] one line each

// ---------------------------------------------------------------------------
__device__ __forceinline__ float sigf(float x) { return 1.0f / (1.0f + __expf(-x)); }
__device__ __forceinline__ float tanhfast(float x) { return 1.0f - 2.0f / (__expf(2.0f * x) + 1.0f); }

__device__ __forceinline__ unsigned ld_acq(const unsigned* p) {
    unsigned v;
    asm volatile("ld.acquire.gpu.u32 %0, [%1];" : "=r"(v) : "l"(p));
    return v;
}
__device__ __forceinline__ void red_release(unsigned* p) {
    asm volatile("red.release.gpu.global.add.u32 [%0], %1;" :: "l"(p), "r"(1u) : "memory");
}
__device__ __forceinline__ void ffma2(ull& acc, ull a, ull b) {
    asm("fma.rn.f32x2 %0, %1, %2, %0;" : "+l"(acc) : "l"(a), "l"(b));
}
// bounded hot-spin then nanosleep backoff (defensive: caps poll pressure)
__device__ __forceinline__ void wait_ge(unsigned* p, unsigned target) {
    int hot = 2048;
    while (ld_acq(p) < target) {
        if (--hot < 0) __nanosleep(256);
    }
}

__global__ void reset_kernel() {
    ((unsigned*)g_bar)[threadIdx.x] = 0u;   // 128 words
}

// ---------------------------------------------------------------------------
// Tiled FP32 GEMM: out[m,n] = sum_k A[m,k] * W[n,k] + bias[n]
// BM=128, BN=64, BK=16, 256 threads, 8x4 per-thread tile.
// SRC: 0 = A param (x), 1 = g_hcat0, 2 = g_ctx
// EPI: 0 = proj (writes g_xp, dual dir weights), 1 = head (writes out param)
// ---------------------------------------------------------------------------
template <int SRC, int EPI>
__global__ __launch_bounds__(256) void gemm_kernel(
    const float* __restrict__ A_in, int K,
    const float* __restrict__ Wf, const float* __restrict__ Wb,
    const float* __restrict__ bf, const float* __restrict__ bb,
    float* __restrict__ out_p)
{
    __shared__ float As[16][132];
    __shared__ float Bs[16][68];

    const float* A = (SRC == 0) ? A_in : (SRC == 1 ? g_hcat0 : g_ctx);

    const int t  = threadIdx.x;
    const int tx = t & 15;
    const int ty = t >> 4;
    const int m0 = blockIdx.x * 128;
    const int n0 = blockIdx.y * 64;

    const float* Wp;
    const float* biasp;
    int wrow0;
    if (EPI == 0) {
        if (n0 < 1024) { Wp = Wf; biasp = bf; wrow0 = n0; }
        else           { Wp = Wb; biasp = bb; wrow0 = n0 - 1024; }
    } else {
        Wp = Wf; biasp = bf; wrow0 = n0;
    }

    float acc[8][4];
#pragma unroll
    for (int i = 0; i < 8; i++)
#pragma unroll
        for (int j = 0; j < 4; j++) acc[i][j] = 0.0f;

    const int nkt = K >> 4;
    for (int kt = 0; kt < nkt; kt++) {
        const int k0 = kt << 4;
#pragma unroll
        for (int r = 0; r < 2; r++) {
            int idx = t + r * 256;
            int row = idx >> 2;
            int kq  = idx & 3;
            float4 v = *(const float4*)&A[(size_t)(m0 + row) * K + k0 + kq * 4];
            As[kq * 4 + 0][row] = v.x;
            As[kq * 4 + 1][row] = v.y;
            As[kq * 4 + 2][row] = v.z;
            As[kq * 4 + 3][row] = v.w;
        }
        {
            int row = t >> 2;
            int kq  = t & 3;
            float4 v = *(const float4*)&Wp[(size_t)(wrow0 + row) * K + k0 + kq * 4];
            Bs[kq * 4 + 0][row] = v.x;
            Bs[kq * 4 + 1][row] = v.y;
            Bs[kq * 4 + 2][row] = v.z;
            Bs[kq * 4 + 3][row] = v.w;
        }
        __syncthreads();
#pragma unroll
        for (int kk = 0; kk < 16; kk++) {
            float af[8], bfr[4];
            *(float4*)&af[0]  = *(const float4*)&As[kk][ty * 8];
            *(float4*)&af[4]  = *(const float4*)&As[kk][ty * 8 + 4];
            *(float4*)&bfr[0] = *(const float4*)&Bs[kk][tx * 4];
#pragma unroll
            for (int i = 0; i < 8; i++)
#pragma unroll
                for (int j = 0; j < 4; j++)
                    acc[i][j] = fmaf(af[i], bfr[j], acc[i][j]);
        }
        __syncthreads();
    }

#pragma unroll
    for (int i = 0; i < 8; i++) {
        int m = m0 + ty * 8 + i;
        int b = m >> 10;
        int s = m & 1023;
#pragma unroll
        for (int j = 0; j < 4; j++) {
            int c = tx * 4 + j;
            float v = acc[i][j] + biasp[wrow0 + c];
            if (EPI == 0) {
                int ng  = n0 + c;
                int dir = ng >> 10;
                int g   = ng & 1023;
                g_xp[((size_t)(dir * SS + s) * BB + b) * G4H + g] = v;
            } else {
                out_p[(size_t)m * 128 + (n0 + c)] = v;
            }
        }
    }
}

// ---------------------------------------------------------------------------
// Persistent bidirectional LSTM layer. 128 CTAs (64/dir), 128 threads.
// CTA owns 4 hidden units (16 W_hh rows, SMEM). Per-direction counter
// barrier: t0 red.release arrival + t0-only ld.acquire spin (1 addr, 64
// pollers). No fences, no L1 flush. f32x2 packed FMAs over k-pairs.
// ---------------------------------------------------------------------------
#define WST 258                         // padded k-stride (floats)
#define LSTM_SMEM ((16 * WST + 32 * WST + 512) * 4)

__global__ __launch_bounds__(128, 1) void lstm_kernel(
    const float* __restrict__ whf, const float* __restrict__ whb, int layer)
{
    extern __shared__ float sm[];
    float* sm_w = sm;                    // [16][WST]
    float* sm_h = sm + 16 * WST;         // [32][WST]
    float* sm_g = sm + 48 * WST;         // [16][32]

    const int t     = threadIdx.x;
    const int dir   = blockIdx.x >> 6;
    const int slice = blockIdx.x & 63;
    const float* W  = dir ? whb : whf;
    float* hout     = (layer == 0) ? g_hcat0 : g_hcat1;
    unsigned* bar   = &g_bar[layer * 2 + dir][0];

    // load weight slice: rows r = G*4+u -> W[(G*256 + slice*4 + u)][k]
    for (int e = t; e < 4096; e += 128) {
        int r = e >> 8, k = e & 255;
        int grow = ((r >> 2) << 8) + (slice << 2) + (r & 3);
        sm_w[r * WST + k] = W[(size_t)grow * HH + k];
    }

    // compute mapping: 2 rows x 2 batches (bp, bp+16) per thread
    const int rp = t >> 4;               // 0..7
    const int bp = t & 15;               // 0..15
    const int r0 = rp * 2, r1 = rp * 2 + 1;
    const int gr0 = ((r0 >> 2) << 8) + (slice << 2) + (r0 & 3);
    const int gr1 = ((r1 >> 2) << 8) + (slice << 2) + (r1 & 3);

    // activation mapping: one (u, b) per thread; warp-coalesced units
    const int au = t & 3;                // 0..3
    const int ab = t >> 2;               // 0..31
    const int myu = (slice << 2) + au;
    float cstate = 0.0f;

    // init h parity 0 (layout [dir][parity][b][k])
    __stcg(&g_h[((dir * 2 + 0) * BB + ab) * HH + myu], 0.0f);

    // barrier phase 1 (init visible)
    unsigned phase = 1;
    __syncthreads();
    if (t == 0) {
        red_release(bar);
        wait_ge(bar, 64u * phase);
    }
    __syncthreads();

    const float* xpd = g_xp + (size_t)dir * SS * BB * G4H;

    for (int s = 0; s < SS; s++) {
        const int p    = s & 1;
        const int tcur = dir ? (SS - 1 - s) : s;

        // prefetch xp for this thread's 4 outputs
        const float* xpb = xpd + (size_t)tcur * BB * G4H;
        float x00 = __ldcg(&xpb[(size_t)bp * G4H + gr0]);
        float x01 = __ldcg(&xpb[(size_t)(bp + 16) * G4H + gr0]);
        float x10 = __ldcg(&xpb[(size_t)bp * G4H + gr1]);
        float x11 = __ldcg(&xpb[(size_t)(bp + 16) * G4H + gr1]);

        // stage h_prev [b][k] -> padded smem (L2-direct loads)
        {
            const float4* gsrc = (const float4*)(g_h + (dir * 2 + p) * BB * HH);
            for (int e = t; e < 2048; e += 128) {
                float4 v = __ldcg(gsrc + e);
                int row = e >> 6;
                int col = e & 63;
                float2* d = (float2*)(sm_h + row * WST) + col * 2;
                d[0] = make_float2(v.x, v.y);
                d[1] = make_float2(v.z, v.w);
            }
        }
        __syncthreads();

        // 2 rows x 2 batches, packed f32x2 over k-pairs
        ull a00 = 0ull, a01 = 0ull, a10 = 0ull, a11 = 0ull;
        const ull* pw0 = (const ull*)(sm_w + r0 * WST);
        const ull* pw1 = (const ull*)(sm_w + r1 * WST);
        const ull* ph0 = (const ull*)(sm_h + bp * WST);
        const ull* ph1 = (const ull*)(sm_h + (bp + 16) * WST);
#pragma unroll 8
        for (int kk = 0; kk < 128; kk++) {
            ull w0 = pw0[kk];
            ull w1 = pw1[kk];
            ull h0 = ph0[kk];
            ull h1 = ph1[kk];
            ffma2(a00, w0, h0);
            ffma2(a01, w0, h1);
            ffma2(a10, w1, h0);
            ffma2(a11, w1, h1);
        }
        {
            float2 v00 = *(float2*)&a00, v01 = *(float2*)&a01;
            float2 v10 = *(float2*)&a10, v11 = *(float2*)&a11;
            sm_g[r0 * 32 + bp]      = v00.x + v00.y + x00;
            sm_g[r0 * 32 + bp + 16] = v01.x + v01.y + x01;
            sm_g[r1 * 32 + bp]      = v10.x + v10.y + x10;
            sm_g[r1 * 32 + bp + 16] = v11.x + v11.y + x11;
        }
        __syncthreads();

        // activation: gates i,f,g,o at rows G*4+u
        {
            float gi = sm_g[(0 * 4 + au) * 32 + ab];
            float gf = sm_g[(1 * 4 + au) * 32 + ab];
            float gg = sm_g[(2 * 4 + au) * 32 + ab];
            float go = sm_g[(3 * 4 + au) * 32 + ab];
            cstate = sigf(gf) * cstate + sigf(gi) * tanhfast(gg);
            float hv = sigf(go) * tanhfast(cstate);
            __stcg(&g_h[((dir * 2 + (p ^ 1)) * BB + ab) * HH + myu], hv);
            __stcg(&hout[((size_t)ab * SS + tcur) * HCAT + dir * HH + myu], hv);
        }

        if (s == SS - 1) break;

        // per-direction counter barrier (red.release arrive, t0-only poll)
        phase++;
        __syncthreads();
        if (t == 0) {
            red_release(bar);
            wait_ge(bar, 64u * phase);
        }
        __syncthreads();
    }
}

// ---------------------------------------------------------------------------
// attention score: s[b,t] = dot(h[b,t,:], attn_w) + attn_b ; per-b max
// ---------------------------------------------------------------------------
__global__ __launch_bounds__(256) void score_kernel(
    const float* __restrict__ attn_w, const float* __restrict__ attn_b)
{
    __shared__ float aw[HCAT];
    __shared__ float red[8];
    const int b = blockIdx.x;
    const int t = threadIdx.x;
    const int w = t >> 5, l = t & 31;
    for (int j = t; j < HCAT; j += 256) aw[j] = attn_w[j];
    __syncthreads();

    const float ab = attn_b[0];
    float mloc = -1e30f;
    for (int tt = w; tt < SS; tt += 8) {
        const float* hp = g_hcat1 + ((size_t)b * SS + tt) * HCAT;
        float sum = 0.f;
        for (int j = l; j < HCAT; j += 32) sum = fmaf(hp[j], aw[j], sum);
#pragma unroll
        for (int o = 16; o > 0; o >>= 1) sum += __shfl_xor_sync(0xFFFFFFFFu, sum, o);
        float sv = sum + ab;
        if (l == 0) g_s[b * SS + tt] = sv;
        mloc = fmaxf(mloc, sv);
    }
    if (l == 0) red[w] = mloc;
    __syncthreads();
    if (t == 0) {
        float m = red[0];
#pragma unroll
        for (int i = 1; i < 8; i++) m = fmaxf(m, red[i]);
        g_mx[b] = m;
    }
}

// ---------------------------------------------------------------------------
// cumulative softmax context: ctx[b,t,:] = cumsum(e*h)/cumsum(e)
// ---------------------------------------------------------------------------
__global__ __launch_bounds__(512) void ctx_kernel()
{
    const int b = blockIdx.x;
    const int j = threadIdx.x;
    const float mx = g_mx[b];
    float num = 0.f, den = 0.f;
    const float* sb = g_s + b * SS;
    for (int t = 0; t < SS; t++) {
        float e = __expf(sb[t] - mx);
        den += e;
        size_t off = ((size_t)b * SS + t) * HCAT + j;
        num = fmaf(e, g_hcat1[off], num);
        g_ctx[off] = num / den;
    }
}

// ---------------------------------------------------------------------------
extern "C" void kernel_launch(void* const* d_in, const int* in_sizes, int n_in,
                              void* d_out, int out_size)
{
    const float* x        = (const float*)d_in[0];
    const float* w_ih_l0f = (const float*)d_in[1];
    const float* w_hh_l0f = (const float*)d_in[2];
    const float* b_l0f    = (const float*)d_in[3];
    const float* w_ih_l0b = (const float*)d_in[4];
    const float* w_hh_l0b = (const float*)d_in[5];
    const float* b_l0b    = (const float*)d_in[6];
    const float* w_ih_l1f = (const float*)d_in[7];
    const float* w_hh_l1f = (const float*)d_in[8];
    const float* b_l1f    = (const float*)d_in[9];
    const float* w_ih_l1b = (const float*)d_in[10];
    const float* w_hh_l1b = (const float*)d_in[11];
    const float* b_l1b    = (const float*)d_in[12];
    const float* attn_w   = (const float*)d_in[13];
    const float* attn_b   = (const float*)d_in[14];
    const float* head_w   = (const float*)d_in[15];
    const float* head_b   = (const float*)d_in[16];
    float* out = (float*)d_out;

    cudaFuncSetAttribute(lstm_kernel, cudaFuncAttributeMaxDynamicSharedMemorySize, LSTM_SMEM);

    reset_kernel<<<1, 128>>>();

    // layer 0: projection + recurrence
    gemm_kernel<0, 0><<<dim3(256, 32), 256>>>(x, DIN, w_ih_l0f, w_ih_l0b, b_l0f, b_l0b, nullptr);
    lstm_kernel<<<128, 128, LSTM_SMEM>>>(w_hh_l0f, w_hh_l0b, 0);

    // layer 1: projection (A = g_hcat0) + recurrence
    gemm_kernel<1, 0><<<dim3(256, 32), 256>>>(nullptr, HCAT, w_ih_l1f, w_ih_l1b, b_l1f, b_l1b, nullptr);
    lstm_kernel<<<128, 128, LSTM_SMEM>>>(w_hh_l1f, w_hh_l1b, 1);

    // attention + context + head
    score_kernel<<<32, 256>>>(attn_w, attn_b);
    ctx_kernel<<<32, 512>>>();
    gemm_kernel<2, 1><<<dim3(256, 2), 256>>>(nullptr, HCAT, head_w, nullptr, head_b, nullptr, out);
}

// round 8
// speedup vs baseline: 1.7321x; 1.0302x over previous
#include <cuda_runtime.h>
#include <cuda_bf16.h>
#include <math.h>

// Problem constants
#define BB 32
#define SS 1024
#define DIN 128
#define HH 256
#define G4H 1024          // 4*H
#define HCAT 512          // 2*H

typedef unsigned long long ull;

// ---------------- scratch (device globals; no cudaMalloc allowed) ----------
__device__ float g_xp[2u * SS * BB * G4H];        // [dir][s][b][4H]
__device__ float g_hcat0[(size_t)BB * SS * HCAT]; // [b][s][512]
__device__ float g_hcat1[(size_t)BB * SS * HCAT];
__device__ float g_ctx[(size_t)BB * SS * HCAT];
__device__ float g_h[2 * 2 * HH * BB];            // [dir][parity][k][b]
__device__ float g_s[BB * SS];
__device__ float g_mx[BB];
__device__ unsigned g_bar[4][32];                 // [layer*2+dir][pad] one line each

// ---------------------------------------------------------------------------
__device__ __forceinline__ float sigf(float x) { return 1.0f / (1.0f + __expf(-x)); }
__device__ __forceinline__ float tanhfast(float x) { return 1.0f - 2.0f / (__expf(2.0f * x) + 1.0f); }

__device__ __forceinline__ unsigned ld_acq(const unsigned* p) {
    unsigned v;
    asm volatile("ld.acquire.gpu.u32 %0, [%1];" : "=r"(v) : "l"(p));
    return v;
}
__device__ __forceinline__ void red_release(unsigned* p) {
    asm volatile("red.release.gpu.global.add.u32 [%0], %1;" :: "l"(p), "r"(1u) : "memory");
}
__device__ __forceinline__ void ffma2(ull& acc, ull a, ull b) {
    asm("fma.rn.f32x2 %0, %1, %2, %0;" : "+l"(acc) : "l"(a), "l"(b));
}
// bounded hot-spin then nanosleep backoff (defensive: caps poll pressure)
__device__ __forceinline__ void wait_ge(unsigned* p, unsigned target) {
    int hot = 2048;
    while (ld_acq(p) < target) {
        if (--hot < 0) __nanosleep(256);
    }
}

__global__ void reset_kernel() {
    ((unsigned*)g_bar)[threadIdx.x] = 0u;   // 128 words
}

// dummy kernel: shifts the ncu-profiled launch slot (index 3) onto lstm layer 0
__global__ void dummy_kernel() {}

// ---------------------------------------------------------------------------
// Tiled FP32 GEMM: out[m,n] = sum_k A[m,k] * W[n,k] + bias[n]
// BM=128, BN=64, BK=16, 256 threads, 8x4 per-thread tile.
// SRC: 0 = A param (x), 1 = g_hcat0, 2 = g_ctx
// EPI: 0 = proj (writes g_xp, dual dir weights), 1 = head (writes out param)
// ---------------------------------------------------------------------------
template <int SRC, int EPI>
__global__ __launch_bounds__(256) void gemm_kernel(
    const float* __restrict__ A_in, int K,
    const float* __restrict__ Wf, const float* __restrict__ Wb,
    const float* __restrict__ bf, const float* __restrict__ bb,
    float* __restrict__ out_p)
{
    __shared__ float As[16][132];
    __shared__ float Bs[16][68];

    const float* A = (SRC == 0) ? A_in : (SRC == 1 ? g_hcat0 : g_ctx);

    const int t  = threadIdx.x;
    const int tx = t & 15;
    const int ty = t >> 4;
    const int m0 = blockIdx.x * 128;
    const int n0 = blockIdx.y * 64;

    const float* Wp;
    const float* biasp;
    int wrow0;
    if (EPI == 0) {
        if (n0 < 1024) { Wp = Wf; biasp = bf; wrow0 = n0; }
        else           { Wp = Wb; biasp = bb; wrow0 = n0 - 1024; }
    } else {
        Wp = Wf; biasp = bf; wrow0 = n0;
    }

    float acc[8][4];
#pragma unroll
    for (int i = 0; i < 8; i++)
#pragma unroll
        for (int j = 0; j < 4; j++) acc[i][j] = 0.0f;

    const int nkt = K >> 4;
    for (int kt = 0; kt < nkt; kt++) {
        const int k0 = kt << 4;
#pragma unroll
        for (int r = 0; r < 2; r++) {
            int idx = t + r * 256;
            int row = idx >> 2;
            int kq  = idx & 3;
            float4 v = *(const float4*)&A[(size_t)(m0 + row) * K + k0 + kq * 4];
            As[kq * 4 + 0][row] = v.x;
            As[kq * 4 + 1][row] = v.y;
            As[kq * 4 + 2][row] = v.z;
            As[kq * 4 + 3][row] = v.w;
        }
        {
            int row = t >> 2;
            int kq  = t & 3;
            float4 v = *(const float4*)&Wp[(size_t)(wrow0 + row) * K + k0 + kq * 4];
            Bs[kq * 4 + 0][row] = v.x;
            Bs[kq * 4 + 1][row] = v.y;
            Bs[kq * 4 + 2][row] = v.z;
            Bs[kq * 4 + 3][row] = v.w;
        }
        __syncthreads();
#pragma unroll
        for (int kk = 0; kk < 16; kk++) {
            float af[8], bfr[4];
            *(float4*)&af[0]  = *(const float4*)&As[kk][ty * 8];
            *(float4*)&af[4]  = *(const float4*)&As[kk][ty * 8 + 4];
            *(float4*)&bfr[0] = *(const float4*)&Bs[kk][tx * 4];
#pragma unroll
            for (int i = 0; i < 8; i++)
#pragma unroll
                for (int j = 0; j < 4; j++)
                    acc[i][j] = fmaf(af[i], bfr[j], acc[i][j]);
        }
        __syncthreads();
    }

#pragma unroll
    for (int i = 0; i < 8; i++) {
        int m = m0 + ty * 8 + i;
        int b = m >> 10;
        int s = m & 1023;
#pragma unroll
        for (int j = 0; j < 4; j++) {
            int c = tx * 4 + j;
            float v = acc[i][j] + biasp[wrow0 + c];
            if (EPI == 0) {
                int ng  = n0 + c;
                int dir = ng >> 10;
                int g   = ng & 1023;
                g_xp[((size_t)(dir * SS + s) * BB + b) * G4H + g] = v;
            } else {
                out_p[(size_t)m * 128 + (n0 + c)] = v;
            }
        }
    }
}

// ---------------------------------------------------------------------------
// Persistent bidirectional LSTM layer. 128 CTAs (64/dir), 128 threads.
// CTA owns 4 hidden units (16 W_hh rows). h staged k-major [k][b] so the
// inner loop moves ~1.25 B per lane-FMA (1 LDS.64 h-pair + 2 broadcast
// splat-w LDS.64 per 2 FFMA2) instead of 4 B/FMA — smem crossbar no longer
// the bound. Weights pre-splatted to float2 in smem. R7 barrier unchanged.
// ---------------------------------------------------------------------------
#define LSTM_SMEM ((8192 + 8192 + 512) * 4)   // w2 32KB + h 32KB + g 2KB

__global__ __launch_bounds__(128, 1) void lstm_kernel(
    const float* __restrict__ whf, const float* __restrict__ whb, int layer)
{
    extern __shared__ float sm[];
    float* sm_w2 = sm;                   // [16][256] float2 splat (8192 floats)
    float* sm_h  = sm + 8192;            // [256][32] k-major
    float* sm_g  = sm + 16384;           // [16][32]

    const int t     = threadIdx.x;
    const int dir   = blockIdx.x >> 6;
    const int slice = blockIdx.x & 63;
    const float* W  = dir ? whb : whf;
    float* hout     = (layer == 0) ? g_hcat0 : g_hcat1;
    unsigned* bar   = &g_bar[layer * 2 + dir][0];

    // load weight slice, splat each value into float2:
    // local row r (=G*4+u) -> global row grow = G*256 + slice*4 + u
    for (int e = t; e < 4096; e += 128) {
        int r = e >> 8, k = e & 255;
        int grow = ((r >> 2) << 8) + (slice << 2) + (r & 3);
        float v = W[(size_t)grow * HH + k];
        ((float2*)sm_w2)[r * 256 + k] = make_float2(v, v);
    }

    // compute mapping: rows {r2, r2+8} x batch pair {2bp, 2bp+1}
    const int bp = t & 15;               // 0..15
    const int r2 = t >> 4;               // 0..7
    const int ra = r2, rb = r2 + 8;
    const int gra = ((ra >> 2) << 8) + (slice << 2) + (ra & 3);
    const int grb = ((rb >> 2) << 8) + (slice << 2) + (rb & 3);

    // activation mapping: one (u, b) per thread
    const int au = t & 3;                // 0..3
    const int ab = t >> 2;               // 0..31
    const int myu = (slice << 2) + au;
    float cstate = 0.0f;

    // init h parity 0 (layout [dir][parity][k][b])
    __stcg(&g_h[((dir * 2 + 0) * HH + myu) * BB + ab], 0.0f);

    // barrier phase 1 (init visible)
    unsigned phase = 1;
    __syncthreads();
    if (t == 0) {
        red_release(bar);
        wait_ge(bar, 64u * phase);
    }
    __syncthreads();

    const float* xpd = g_xp + (size_t)dir * SS * BB * G4H;

    for (int s = 0; s < SS; s++) {
        const int p    = s & 1;
        const int tcur = dir ? (SS - 1 - s) : s;

        // prefetch xp for this thread's 4 outputs: rows {ra,rb} x b {2bp,2bp+1}
        const float* xpb = xpd + (size_t)tcur * BB * G4H;
        float x00 = __ldcg(&xpb[(size_t)(2 * bp) * G4H + gra]);
        float x01 = __ldcg(&xpb[(size_t)(2 * bp + 1) * G4H + gra]);
        float x10 = __ldcg(&xpb[(size_t)(2 * bp) * G4H + grb]);
        float x11 = __ldcg(&xpb[(size_t)(2 * bp + 1) * G4H + grb]);

        // stage h_prev [k][b] -> smem, straight float4 copy (L2-direct loads)
        {
            const float4* gsrc = (const float4*)(g_h + (dir * 2 + p) * HH * BB);
            float4* dsth = (float4*)sm_h;
            for (int e = t; e < 2048; e += 128) dsth[e] = __ldcg(gsrc + e);
        }
        __syncthreads();

        // 2 rows x 1 batch-pair, f32x2 packed over the batch pair
        ull acc0 = 0ull, acc1 = 0ull;
        const ull* pw0 = (const ull*)(sm_w2 + ra * 512);
        const ull* pw1 = (const ull*)(sm_w2 + rb * 512);
        const float* phh = sm_h + 2 * bp;
#pragma unroll 8
        for (int k = 0; k < 256; k++) {
            ull h2 = *(const ull*)(phh + k * 32);
            ffma2(acc0, pw0[k], h2);
            ffma2(acc1, pw1[k], h2);
        }
        {
            float2 v0 = *(float2*)&acc0;
            float2 v1 = *(float2*)&acc1;
            sm_g[ra * 32 + 2 * bp]     = v0.x + x00;
            sm_g[ra * 32 + 2 * bp + 1] = v0.y + x01;
            sm_g[rb * 32 + 2 * bp]     = v1.x + x10;
            sm_g[rb * 32 + 2 * bp + 1] = v1.y + x11;
        }
        __syncthreads();

        // activation: gates i,f,g,o at local rows G*4+u
        {
            float gi = sm_g[(0 * 4 + au) * 32 + ab];
            float gf = sm_g[(1 * 4 + au) * 32 + ab];
            float gg = sm_g[(2 * 4 + au) * 32 + ab];
            float go = sm_g[(3 * 4 + au) * 32 + ab];
            cstate = sigf(gf) * cstate + sigf(gi) * tanhfast(gg);
            float hv = sigf(go) * tanhfast(cstate);
            __stcg(&g_h[((dir * 2 + (p ^ 1)) * HH + myu) * BB + ab], hv);
            __stcg(&hout[((size_t)ab * SS + tcur) * HCAT + dir * HH + myu], hv);
        }

        if (s == SS - 1) break;

        // per-direction counter barrier (red.release arrive, t0-only poll)
        phase++;
        __syncthreads();
        if (t == 0) {
            red_release(bar);
            wait_ge(bar, 64u * phase);
        }
        __syncthreads();
    }
}

// ---------------------------------------------------------------------------
// attention score: s[b,t] = dot(h[b,t,:], attn_w) + attn_b ; per-b max
// ---------------------------------------------------------------------------
__global__ __launch_bounds__(256) void score_kernel(
    const float* __restrict__ attn_w, const float* __restrict__ attn_b)
{
    __shared__ float aw[HCAT];
    __shared__ float red[8];
    const int b = blockIdx.x;
    const int t = threadIdx.x;
    const int w = t >> 5, l = t & 31;
    for (int j = t; j < HCAT; j += 256) aw[j] = attn_w[j];
    __syncthreads();

    const float ab = attn_b[0];
    float mloc = -1e30f;
    for (int tt = w; tt < SS; tt += 8) {
        const float* hp = g_hcat1 + ((size_t)b * SS + tt) * HCAT;
        float sum = 0.f;
        for (int j = l; j < HCAT; j += 32) sum = fmaf(hp[j], aw[j], sum);
#pragma unroll
        for (int o = 16; o > 0; o >>= 1) sum += __shfl_xor_sync(0xFFFFFFFFu, sum, o);
        float sv = sum + ab;
        if (l == 0) g_s[b * SS + tt] = sv;
        mloc = fmaxf(mloc, sv);
    }
    if (l == 0) red[w] = mloc;
    __syncthreads();
    if (t == 0) {
        float m = red[0];
#pragma unroll
        for (int i = 1; i < 8; i++) m = fmaxf(m, red[i]);
        g_mx[b] = m;
    }
}

// ---------------------------------------------------------------------------
// cumulative softmax context: ctx[b,t,:] = cumsum(e*h)/cumsum(e)
// ---------------------------------------------------------------------------
__global__ __launch_bounds__(512) void ctx_kernel()
{
    const int b = blockIdx.x;
    const int j = threadIdx.x;
    const float mx = g_mx[b];
    float num = 0.f, den = 0.f;
    const float* sb = g_s + b * SS;
#pragma unroll 4
    for (int t = 0; t < SS; t++) {
        float e = __expf(sb[t] - mx);
        den += e;
        size_t off = ((size_t)b * SS + t) * HCAT + j;
        num = fmaf(e, __ldg(&g_hcat1[off]), num);
        g_ctx[off] = __fdividef(num, den);
    }
}

// ---------------------------------------------------------------------------
extern "C" void kernel_launch(void* const* d_in, const int* in_sizes, int n_in,
                              void* d_out, int out_size)
{
    const float* x        = (const float*)d_in[0];
    const float* w_ih_l0f = (const float*)d_in[1];
    const float* w_hh_l0f = (const float*)d_in[2];
    const float* b_l0f    = (const float*)d_in[3];
    const float* w_ih_l0b = (const float*)d_in[4];
    const float* w_hh_l0b = (const float*)d_in[5];
    const float* b_l0b    = (const float*)d_in[6];
    const float* w_ih_l1f = (const float*)d_in[7];
    const float* w_hh_l1f = (const float*)d_in[8];
    const float* b_l1f    = (const float*)d_in[9];
    const float* w_ih_l1b = (const float*)d_in[10];
    const float* w_hh_l1b = (const float*)d_in[11];
    const float* b_l1b    = (const float*)d_in[12];
    const float* attn_w   = (const float*)d_in[13];
    const float* attn_b   = (const float*)d_in[14];
    const float* head_w   = (const float*)d_in[15];
    const float* head_b   = (const float*)d_in[16];
    float* out = (float*)d_out;

    cudaFuncSetAttribute(lstm_kernel, cudaFuncAttributeMaxDynamicSharedMemorySize, LSTM_SMEM);

    reset_kernel<<<1, 128>>>();                                   // idx 0

    // layer 0: projection + recurrence (dummy shifts lstm0 into ncu slot 3)
    gemm_kernel<0, 0><<<dim3(256, 32), 256>>>(x, DIN, w_ih_l0f, w_ih_l0b, b_l0f, b_l0b, nullptr);   // idx 1
    dummy_kernel<<<1, 32>>>();                                    // idx 2
    lstm_kernel<<<128, 128, LSTM_SMEM>>>(w_hh_l0f, w_hh_l0b, 0);  // idx 3  <- profiled
    // layer 1: projection (A = g_hcat0) + recurrence
    gemm_kernel<1, 0><<<dim3(256, 32), 256>>>(nullptr, HCAT, w_ih_l1f, w_ih_l1b, b_l1f, b_l1b, nullptr);
    lstm_kernel<<<128, 128, LSTM_SMEM>>>(w_hh_l1f, w_hh_l1b, 1);

    // attention + context + head
    score_kernel<<<32, 256>>>(attn_w, attn_b);
    ctx_kernel<<<32, 512>>>();
    gemm_kernel<2, 1><<<dim3(256, 2), 256>>>(nullptr, HCAT, head_w, nullptr, head_b, nullptr, out);
}

// round 9
// speedup vs baseline: 1.7453x; 1.0076x over previous
#include <cuda_runtime.h>
#include <cuda_bf16.h>
#include <math.h>

// Problem constants
#define BB 32
#define SS 1024
#define DIN 128
#define HH 256
#define G4H 1024          // 4*H
#define HCAT 512          // 2*H

typedef unsigned long long ull;

// ---------------- scratch (device globals; no cudaMalloc allowed) ----------
__device__ float g_xp[2u * SS * BB * G4H];        // [dir][s][b][4H]
__device__ float g_hcat0[(size_t)BB * SS * HCAT]; // [b][s][512]
__device__ float g_hcat1[(size_t)BB * SS * HCAT];
__device__ float g_ctx[(size_t)BB * SS * HCAT];
__device__ float g_h[2 * 2 * HH * BB];            // [dir][parity][k][b]
__device__ float g_s[BB * SS];
__device__ float g_mx[BB];
__device__ unsigned g_bar[4][8][32];              // [layer*2+dir][counter][pad128B]

// ---------------------------------------------------------------------------
__device__ __forceinline__ float sigf(float x) { return 1.0f / (1.0f + __expf(-x)); }
__device__ __forceinline__ float tanhfast(float x) { return 1.0f - 2.0f / (__expf(2.0f * x) + 1.0f); }

__device__ __forceinline__ unsigned ld_acq(const unsigned* p) {
    unsigned v;
    asm volatile("ld.acquire.gpu.u32 %0, [%1];" : "=r"(v) : "l"(p));
    return v;
}
__device__ __forceinline__ void red_release(unsigned* p) {
    asm volatile("red.release.gpu.global.add.u32 [%0], %1;" :: "l"(p), "r"(1u) : "memory");
}
__device__ __forceinline__ void ffma2(ull& acc, ull a, ull b) {
    asm("fma.rn.f32x2 %0, %1, %2, %0;" : "+l"(acc) : "l"(a), "l"(b));
}
// bounded hot-spin then nanosleep backoff (defensive: caps poll pressure)
__device__ __forceinline__ void wait_ge(unsigned* p, unsigned target) {
    int hot = 2048;
    while (ld_acq(p) < target) {
        if (--hot < 0) __nanosleep(256);
    }
}

__global__ void reset_kernel() {
    ((unsigned*)g_bar)[threadIdx.x] = 0u;   // 4*8*32 = 1024 words
}

// dummy kernel: shifts the ncu-profiled launch slot (index 3) onto lstm layer 0
__global__ void dummy_kernel() {}

// ---------------------------------------------------------------------------
// Tiled FP32 GEMM: out[m,n] = sum_k A[m,k] * W[n,k] + bias[n]
// BM=128, BN=64, BK=16, 256 threads, 8x4 per-thread tile.
// SRC: 0 = A param (x), 1 = g_hcat0, 2 = g_ctx
// EPI: 0 = proj (writes g_xp, dual dir weights), 1 = head (writes out param)
// ---------------------------------------------------------------------------
template <int SRC, int EPI>
__global__ __launch_bounds__(256) void gemm_kernel(
    const float* __restrict__ A_in, int K,
    const float* __restrict__ Wf, const float* __restrict__ Wb,
    const float* __restrict__ bf, const float* __restrict__ bb,
    float* __restrict__ out_p)
{
    __shared__ float As[16][132];
    __shared__ float Bs[16][68];

    const float* A = (SRC == 0) ? A_in : (SRC == 1 ? g_hcat0 : g_ctx);

    const int t  = threadIdx.x;
    const int tx = t & 15;
    const int ty = t >> 4;
    const int m0 = blockIdx.x * 128;
    const int n0 = blockIdx.y * 64;

    const float* Wp;
    const float* biasp;
    int wrow0;
    if (EPI == 0) {
        if (n0 < 1024) { Wp = Wf; biasp = bf; wrow0 = n0; }
        else           { Wp = Wb; biasp = bb; wrow0 = n0 - 1024; }
    } else {
        Wp = Wf; biasp = bf; wrow0 = n0;
    }

    float acc[8][4];
#pragma unroll
    for (int i = 0; i < 8; i++)
#pragma unroll
        for (int j = 0; j < 4; j++) acc[i][j] = 0.0f;

    const int nkt = K >> 4;
    for (int kt = 0; kt < nkt; kt++) {
        const int k0 = kt << 4;
#pragma unroll
        for (int r = 0; r < 2; r++) {
            int idx = t + r * 256;
            int row = idx >> 2;
            int kq  = idx & 3;
            float4 v = *(const float4*)&A[(size_t)(m0 + row) * K + k0 + kq * 4];
            As[kq * 4 + 0][row] = v.x;
            As[kq * 4 + 1][row] = v.y;
            As[kq * 4 + 2][row] = v.z;
            As[kq * 4 + 3][row] = v.w;
        }
        {
            int row = t >> 2;
            int kq  = t & 3;
            float4 v = *(const float4*)&Wp[(size_t)(wrow0 + row) * K + k0 + kq * 4];
            Bs[kq * 4 + 0][row] = v.x;
            Bs[kq * 4 + 1][row] = v.y;
            Bs[kq * 4 + 2][row] = v.z;
            Bs[kq * 4 + 3][row] = v.w;
        }
        __syncthreads();
#pragma unroll
        for (int kk = 0; kk < 16; kk++) {
            float af[8], bfr[4];
            *(float4*)&af[0]  = *(const float4*)&As[kk][ty * 8];
            *(float4*)&af[4]  = *(const float4*)&As[kk][ty * 8 + 4];
            *(float4*)&bfr[0] = *(const float4*)&Bs[kk][tx * 4];
#pragma unroll
            for (int i = 0; i < 8; i++)
#pragma unroll
                for (int j = 0; j < 4; j++)
                    acc[i][j] = fmaf(af[i], bfr[j], acc[i][j]);
        }
        __syncthreads();
    }

#pragma unroll
    for (int i = 0; i < 8; i++) {
        int m = m0 + ty * 8 + i;
        int b = m >> 10;
        int s = m & 1023;
#pragma unroll
        for (int j = 0; j < 4; j++) {
            int c = tx * 4 + j;
            float v = acc[i][j] + biasp[wrow0 + c];
            if (EPI == 0) {
                int ng  = n0 + c;
                int dir = ng >> 10;
                int g   = ng & 1023;
                g_xp[((size_t)(dir * SS + s) * BB + b) * G4H + g] = v;
            } else {
                out_p[(size_t)m * 128 + (n0 + c)] = v;
            }
        }
    }
}

// ---------------------------------------------------------------------------
// Persistent bidirectional LSTM layer. 128 CTAs (64/dir), 128 threads.
// CTA owns 4 hidden units (16 W_hh rows). h k-major [k][b] in smem; W
// pre-splatted float2, read as LDS.128 over k-pairs (2 LDS.128 w + 2
// LDS.64 h + 4 FFMA2 per 2k). Barrier: 8 distributed arrival counters
// (red.release), lanes 0-7 poll one counter each.
// ---------------------------------------------------------------------------
#define LSTM_SMEM ((8192 + 8192 + 512) * 4)   // w2 32KB + h 32KB + g 2KB

__global__ __launch_bounds__(128, 1) void lstm_kernel(
    const float* __restrict__ whf, const float* __restrict__ whb, int layer)
{
    extern __shared__ float sm[];
    float* sm_w2 = sm;                   // [16 rows][256 k] float2 splat
    float* sm_h  = sm + 8192;            // [256][32] k-major
    float* sm_g  = sm + 16384;           // [16][32]

    const int t     = threadIdx.x;
    const int dir   = blockIdx.x >> 6;
    const int slice = blockIdx.x & 63;
    const float* W  = dir ? whb : whf;
    float* hout     = (layer == 0) ? g_hcat0 : g_hcat1;
    unsigned* barr  = &g_bar[layer * 2 + dir][0][0];   // counters at barr + c*32
    unsigned* myctr = barr + (slice & 7) * 32;

    // load weight slice, splat each value into float2:
    // local row r (=G*4+u) -> global row grow = G*256 + slice*4 + u
    for (int e = t; e < 4096; e += 128) {
        int r = e >> 8, k = e & 255;
        int grow = ((r >> 2) << 8) + (slice << 2) + (r & 3);
        float v = W[(size_t)grow * HH + k];
        ((float2*)sm_w2)[r * 256 + k] = make_float2(v, v);
    }

    // compute mapping: rows {r2, r2+8} x batch pair {2bp, 2bp+1}
    const int bp = t & 15;               // 0..15
    const int r2 = t >> 4;               // 0..7
    const int ra = r2, rb = r2 + 8;
    const int gra = ((ra >> 2) << 8) + (slice << 2) + (ra & 3);
    const int grb = ((rb >> 2) << 8) + (slice << 2) + (rb & 3);

    // activation mapping: one (u, b) per thread
    const int au = t & 3;                // 0..3
    const int ab = t >> 2;               // 0..31
    const int myu = (slice << 2) + au;
    float cstate = 0.0f;

    // init h parity 0 (layout [dir][parity][k][b])
    __stcg(&g_h[((dir * 2 + 0) * HH + myu) * BB + ab], 0.0f);

    // barrier phase 1 (init visible)
    unsigned phase = 1;
    __syncthreads();
    if (t == 0) red_release(myctr);
    if (t < 8) wait_ge(barr + t * 32, 8u * phase);
    __syncthreads();

    const float* xpd = g_xp + (size_t)dir * SS * BB * G4H;

    for (int s = 0; s < SS; s++) {
        const int p    = s & 1;
        const int tcur = dir ? (SS - 1 - s) : s;

        // prefetch xp for this thread's 4 outputs: rows {ra,rb} x b {2bp,2bp+1}
        const float* xpb = xpd + (size_t)tcur * BB * G4H;
        float x00 = __ldcg(&xpb[(size_t)(2 * bp) * G4H + gra]);
        float x01 = __ldcg(&xpb[(size_t)(2 * bp + 1) * G4H + gra]);
        float x10 = __ldcg(&xpb[(size_t)(2 * bp) * G4H + grb]);
        float x11 = __ldcg(&xpb[(size_t)(2 * bp + 1) * G4H + grb]);

        // stage h_prev [k][b] -> smem, straight float4 copy (L2-direct loads)
        {
            const float4* gsrc = (const float4*)(g_h + (dir * 2 + p) * HH * BB);
            float4* dsth = (float4*)sm_h;
            for (int e = t; e < 2048; e += 128) dsth[e] = __ldcg(gsrc + e);
        }
        __syncthreads();

        // 2 rows x 1 batch-pair; w as LDS.128 over k-pairs, h as LDS.64
        ull acc0 = 0ull, acc1 = 0ull;
        const longlong2* pw0 = (const longlong2*)(sm_w2 + ra * 512);
        const longlong2* pw1 = (const longlong2*)(sm_w2 + rb * 512);
        const float* phh = sm_h + 2 * bp;
#pragma unroll 8
        for (int kq = 0; kq < 128; kq++) {
            longlong2 w0 = pw0[kq];          // splat(w[ra][2kq]), splat(w[ra][2kq+1])
            longlong2 w1 = pw1[kq];
            ull h0 = *(const ull*)(phh + (2 * kq) * 32);
            ull h1 = *(const ull*)(phh + (2 * kq + 1) * 32);
            ffma2(acc0, (ull)w0.x, h0);
            ffma2(acc0, (ull)w0.y, h1);
            ffma2(acc1, (ull)w1.x, h0);
            ffma2(acc1, (ull)w1.y, h1);
        }
        {
            float2 v0 = *(float2*)&acc0;
            float2 v1 = *(float2*)&acc1;
            sm_g[ra * 32 + 2 * bp]     = v0.x + x00;
            sm_g[ra * 32 + 2 * bp + 1] = v0.y + x01;
            sm_g[rb * 32 + 2 * bp]     = v1.x + x10;
            sm_g[rb * 32 + 2 * bp + 1] = v1.y + x11;
        }
        __syncthreads();

        // activation: gates i,f,g,o at local rows G*4+u
        {
            float gi = sm_g[(0 * 4 + au) * 32 + ab];
            float gf = sm_g[(1 * 4 + au) * 32 + ab];
            float gg = sm_g[(2 * 4 + au) * 32 + ab];
            float go = sm_g[(3 * 4 + au) * 32 + ab];
            cstate = sigf(gf) * cstate + sigf(gi) * tanhfast(gg);
            float hv = sigf(go) * tanhfast(cstate);
            __stcg(&g_h[((dir * 2 + (p ^ 1)) * HH + myu) * BB + ab], hv);
            __stcg(&hout[((size_t)ab * SS + tcur) * HCAT + dir * HH + myu], hv);
        }

        if (s == SS - 1) break;

        // distributed-counter barrier (red.release arrive, 8 lanes poll)
        phase++;
        __syncthreads();
        if (t == 0) red_release(myctr);
        if (t < 8) wait_ge(barr + t * 32, 8u * phase);
        __syncthreads();
    }
}

// ---------------------------------------------------------------------------
// attention score: s[b,t] = dot(h[b,t,:], attn_w) + attn_b ; per-b max
// ---------------------------------------------------------------------------
__global__ __launch_bounds__(256) void score_kernel(
    const float* __restrict__ attn_w, const float* __restrict__ attn_b)
{
    __shared__ float aw[HCAT];
    __shared__ float red[8];
    const int b = blockIdx.x;
    const int t = threadIdx.x;
    const int w = t >> 5, l = t & 31;
    for (int j = t; j < HCAT; j += 256) aw[j] = attn_w[j];
    __syncthreads();

    const float ab = attn_b[0];
    float mloc = -1e30f;
    for (int tt = w; tt < SS; tt += 8) {
        const float* hp = g_hcat1 + ((size_t)b * SS + tt) * HCAT;
        float sum = 0.f;
        for (int j = l; j < HCAT; j += 32) sum = fmaf(hp[j], aw[j], sum);
#pragma unroll
        for (int o = 16; o > 0; o >>= 1) sum += __shfl_xor_sync(0xFFFFFFFFu, sum, o);
        float sv = sum + ab;
        if (l == 0) g_s[b * SS + tt] = sv;
        mloc = fmaxf(mloc, sv);
    }
    if (l == 0) red[w] = mloc;
    __syncthreads();
    if (t == 0) {
        float m = red[0];
#pragma unroll
        for (int i = 1; i < 8; i++) m = fmaxf(m, red[i]);
        g_mx[b] = m;
    }
}

// ---------------------------------------------------------------------------
// cumulative softmax context: ctx[b,t,:] = cumsum(e*h)/cumsum(e)
// ---------------------------------------------------------------------------
__global__ __launch_bounds__(512) void ctx_kernel()
{
    const int b = blockIdx.x;
    const int j = threadIdx.x;
    const float mx = g_mx[b];
    float num = 0.f, den = 0.f;
    const float* sb = g_s + b * SS;
#pragma unroll 4
    for (int t = 0; t < SS; t++) {
        float e = __expf(sb[t] - mx);
        den += e;
        size_t off = ((size_t)b * SS + t) * HCAT + j;
        num = fmaf(e, __ldg(&g_hcat1[off]), num);
        g_ctx[off] = __fdividef(num, den);
    }
}

// ---------------------------------------------------------------------------
extern "C" void kernel_launch(void* const* d_in, const int* in_sizes, int n_in,
                              void* d_out, int out_size)
{
    const float* x        = (const float*)d_in[0];
    const float* w_ih_l0f = (const float*)d_in[1];
    const float* w_hh_l0f = (const float*)d_in[2];
    const float* b_l0f    = (const float*)d_in[3];
    const float* w_ih_l0b = (const float*)d_in[4];
    const float* w_hh_l0b = (const float*)d_in[5];
    const float* b_l0b    = (const float*)d_in[6];
    const float* w_ih_l1f = (const float*)d_in[7];
    const float* w_hh_l1f = (const float*)d_in[8];
    const float* b_l1f    = (const float*)d_in[9];
    const float* w_ih_l1b = (const float*)d_in[10];
    const float* w_hh_l1b = (const float*)d_in[11];
    const float* b_l1b    = (const float*)d_in[12];
    const float* attn_w   = (const float*)d_in[13];
    const float* attn_b   = (const float*)d_in[14];
    const float* head_w   = (const float*)d_in[15];
    const float* head_b   = (const float*)d_in[16];
    float* out = (float*)d_out;

    cudaFuncSetAttribute(lstm_kernel, cudaFuncAttributeMaxDynamicSharedMemorySize, LSTM_SMEM);

    reset_kernel<<<1, 1024>>>();                                  // idx 0

    // layer 0: projection + recurrence (dummy shifts lstm0 into ncu slot 3)
    gemm_kernel<0, 0><<<dim3(256, 32), 256>>>(x, DIN, w_ih_l0f, w_ih_l0b, b_l0f, b_l0b, nullptr);   // idx 1
    dummy_kernel<<<1, 32>>>();                                    // idx 2
    lstm_kernel<<<128, 128, LSTM_SMEM>>>(w_hh_l0f, w_hh_l0b, 0);  // idx 3  <- profiled
    // layer 1: projection (A = g_hcat0) + recurrence
    gemm_kernel<1, 0><<<dim3(256, 32), 256>>>(nullptr, HCAT, w_ih_l1f, w_ih_l1b, b_l1f, b_l1b, nullptr);
    lstm_kernel<<<128, 128, LSTM_SMEM>>>(w_hh_l1f, w_hh_l1b, 1);

    // attention + context + head
    score_kernel<<<32, 256>>>(attn_w, attn_b);
    ctx_kernel<<<32, 512>>>();
    gemm_kernel<2, 1><<<dim3(256, 2), 256>>>(nullptr, HCAT, head_w, nullptr, head_b, nullptr, out);
}